// round 6
// baseline (speedup 1.0000x reference)
#include <cuda_runtime.h>

// DenselyCnnAttLayer, warp-per-row + L2 prefetch double-row.
// out[b,s,d] = sum_l softmax_m( sum_l' s[b,s,l'] * Ws[s,l',m] )[l] * x_l[b,s,d]
// B=64, S=512, L=6, D=512, fp32. Minimal traffic: 6 reads + 1 write = ~470MB.
//
// R6 vs R3 (ncu 66.5us, DRAM 84.7%): each warp handles TWO rows. Row B's
// 12KB is prefetched to L2 (prefetch.global.L2 -- zero register cost) before
// row A is processed, so row B's DRAM fetch overlaps row A's load-wait and
// compute tail; row B's LDGs then hit L2. 2x memory-level parallelism per
// warp at unchanged register pressure. CTA = 4 warps = 8 rows, grid 4096.

#define DD    512
#define LL    6
#define CHNK  4            // float4 chunks per lane per layer (512/32/4)
#define NTHR  128          // 4 warps per CTA
#define RPW   2            // rows per warp

__device__ __forceinline__ void prefetch_l2(const void* p) {
    asm volatile("prefetch.global.L2 [%0];" :: "l"(p));
}

__device__ __forceinline__ void process_row(
    const float* const xs[LL], const float* __restrict__ Ws,
    float* __restrict__ out, int row, int lane)
{
    const size_t base = (size_t)row * DD + (size_t)lane * 4;

    float4 v[LL][CHNK];
#pragma unroll
    for (int j = 0; j < LL; j++) {
#pragma unroll
        for (int c = 0; c < CHNK; c++) {
            v[j][c] = __ldcs(reinterpret_cast<const float4*>(xs[j] + base + c * 128));
        }
    }

    float p[LL];
#pragma unroll
    for (int j = 0; j < LL; j++) {
        float a0 = (v[j][0].x + v[j][0].y) + (v[j][0].z + v[j][0].w);
        float a1 = (v[j][1].x + v[j][1].y) + (v[j][1].z + v[j][1].w);
        float a2 = (v[j][2].x + v[j][2].y) + (v[j][2].z + v[j][2].w);
        float a3 = (v[j][3].x + v[j][3].y) + (v[j][3].z + v[j][3].w);
        p[j] = (a0 + a1) + (a2 + a3);
    }

    // Warp butterfly: all lanes end with full per-layer sums.
#pragma unroll
    for (int off = 16; off > 0; off >>= 1) {
#pragma unroll
        for (int j = 0; j < LL; j++) {
            p[j] += __shfl_xor_sync(0xffffffffu, p[j], off);
        }
    }

    // Redundant per-lane 6x6 projection + softmax (warp-uniform Ws loads).
    const int s = row & 511;                     // S = 512
    const float* W = Ws + (size_t)s * (LL * LL);
    float logit[LL];
#pragma unroll
    for (int m = 0; m < LL; m++) logit[m] = 0.0f;
#pragma unroll
    for (int l = 0; l < LL; l++) {
        const float sl = p[l];
#pragma unroll
        for (int m = 0; m < LL; m++) {
            logit[m] = fmaf(sl, __ldg(W + l * LL + m), logit[m]);
        }
    }

    float mx = logit[0];
#pragma unroll
    for (int m = 1; m < LL; m++) mx = fmaxf(mx, logit[m]);
    float a[LL];
    float den = 0.0f;
#pragma unroll
    for (int m = 0; m < LL; m++) {
        a[m] = __expf(logit[m] - mx);
        den += a[m];
    }
    const float inv = __frcp_rn(den);
#pragma unroll
    for (int m = 0; m < LL; m++) a[m] *= inv;

    // Weighted combine over layers, 4 coalesced streaming stores.
#pragma unroll
    for (int c = 0; c < CHNK; c++) {
        float4 o;
        o.x = o.y = o.z = o.w = 0.0f;
#pragma unroll
        for (int j = 0; j < LL; j++) {
            o.x = fmaf(a[j], v[j][c].x, o.x);
            o.y = fmaf(a[j], v[j][c].y, o.y);
            o.z = fmaf(a[j], v[j][c].z, o.z);
            o.w = fmaf(a[j], v[j][c].w, o.w);
        }
        __stcs(reinterpret_cast<float4*>(out + base + c * 128), o);
    }
}

__global__ __launch_bounds__(NTHR, 4)
void dense_att_kernel(const float* __restrict__ x0,
                      const float* __restrict__ x1,
                      const float* __restrict__ x2,
                      const float* __restrict__ x3,
                      const float* __restrict__ x4,
                      const float* __restrict__ x5,
                      const float* __restrict__ Ws,   // [S, L, L]
                      float* __restrict__ out)        // [B, S, D]
{
    const int warp = threadIdx.x >> 5;
    const int lane = threadIdx.x & 31;

    // CTA covers 8 consecutive rows; warp w owns rows base+w (A) and base+w+4 (B).
    const int rowA = blockIdx.x * (NTHR / 32) * RPW + warp;
    const int rowB = rowA + (NTHR / 32);

    const float* xs[LL] = {x0, x1, x2, x3, x4, x5};

    // Prefetch row B's 12KB into L2 (16 x 128B lines per layer; lanes 0..15).
    if (lane < 16) {
        const size_t pb = (size_t)rowB * DD + (size_t)lane * 32;
#pragma unroll
        for (int j = 0; j < LL; j++) {
            prefetch_l2(xs[j] + pb);
        }
    }

    process_row(xs, Ws, out, rowA, lane);
    process_row(xs, Ws, out, rowB, lane);
}

extern "C" void kernel_launch(void* const* d_in, const int* in_sizes, int n_in,
                              void* d_out, int out_size)
{
    const float* x0 = (const float*)d_in[0];
    const float* x1 = (const float*)d_in[1];
    const float* x2 = (const float*)d_in[2];
    const float* x3 = (const float*)d_in[3];
    const float* x4 = (const float*)d_in[4];
    const float* x5 = (const float*)d_in[5];
    const float* Ws = (const float*)d_in[6];
    float* out = (float*)d_out;

    const int rows = in_sizes[0] / DD;                 // B*S = 32768
    const int ctas = rows / ((NTHR / 32) * RPW);       // 4096

    dense_att_kernel<<<ctas, NTHR>>>(x0, x1, x2, x3, x4, x5, Ws, out);
}

// round 8
// speedup vs baseline: 1.0853x; 1.0853x over previous
#include <cuda_runtime.h>

// DenselyCnnAttLayer, warp-per-row — converged champion (R3 structure).
// out[b,s,d] = sum_l softmax_m( sum_l' s[b,s,l'] * Ws[s,l',m] )[l] * x_l[b,s,d]
// where s[b,s,l] = sum_d x_l[b,s,d].  B=64, S=512, L=6, D=512, fp32.
//
// Traffic is minimal: 6 reads + 1 write of [B,S,D] = ~470MB. Measured at
// 6.7TB/s (84.7% of spec) == the mixed-stream HBM3e ceiling; ncu time ~66.5us
// matches 470MB / 6.7TB/s exactly, so no waste traffic remains.
//
// Experiment log (all measured, all reverted):
//  R1 block-per-row + barrier:      83.5% DRAM, ncu 69.2us
//  R2 smem payload staging:         72.5% (L1tex pipe contention)
//  R3 warp-per-row, reg payload:    84.7%, ncu 66.5us  <-- this kernel
//  R4 persistent grid-stride:       78.7% (load/compute serialization)
//  R5 TMA ring + mbarrier:          77.9% (1 CTA/SM, wait overhead)
//  R6 L2-prefetch double-row:       72.6% (halved CTA-level MLP)
//  R7 redux.sync.add.f32:           does not exist on sm_103 (int-only)
// Conclusion: HW CTA scheduler rotating 8192 small independent CTAs is the
// best memory-parallelism engine for this stream; kernel is at the HBM roof.

#define DD    512
#define LL    6
#define CHNK  4            // float4 chunks per lane per layer (512/32/4)
#define NTHR  128          // 4 warps = 4 rows per CTA

__global__ __launch_bounds__(NTHR, 4)
void dense_att_kernel(const float* __restrict__ x0,
                      const float* __restrict__ x1,
                      const float* __restrict__ x2,
                      const float* __restrict__ x3,
                      const float* __restrict__ x4,
                      const float* __restrict__ x5,
                      const float* __restrict__ Ws,   // [S, L, L]
                      float* __restrict__ out)        // [B, S, D]
{
    const int warp = threadIdx.x >> 5;
    const int lane = threadIdx.x & 31;
    const int row  = blockIdx.x * (NTHR / 32) + warp;   // b*S + s
    const int s    = row & 511;                          // S = 512

    // lane handles float4s at d = c*128 + lane*4, c = 0..3 (coalesced)
    const size_t base = (size_t)row * DD + (size_t)lane * 4;

    const float* xs[LL] = {x0, x1, x2, x3, x4, x5};

    // 24 front-batched streaming LDG.128 (each element touched exactly once).
    float4 v[LL][CHNK];
#pragma unroll
    for (int j = 0; j < LL; j++) {
#pragma unroll
        for (int c = 0; c < CHNK; c++) {
            v[j][c] = __ldcs(reinterpret_cast<const float4*>(xs[j] + base + c * 128));
        }
    }

    float p[LL];
#pragma unroll
    for (int j = 0; j < LL; j++) {
        float a0 = (v[j][0].x + v[j][0].y) + (v[j][0].z + v[j][0].w);
        float a1 = (v[j][1].x + v[j][1].y) + (v[j][1].z + v[j][1].w);
        float a2 = (v[j][2].x + v[j][2].y) + (v[j][2].z + v[j][2].w);
        float a3 = (v[j][3].x + v[j][3].y) + (v[j][3].z + v[j][3].w);
        p[j] = (a0 + a1) + (a2 + a3);
    }

    // Warp butterfly: all lanes end with the full per-layer sums.
    // (redux.sync.add is integer-only on sm_103 — shuffle tree required.)
#pragma unroll
    for (int off = 16; off > 0; off >>= 1) {
#pragma unroll
        for (int j = 0; j < LL; j++) {
            p[j] += __shfl_xor_sync(0xffffffffu, p[j], off);
        }
    }

    // Redundant per-lane 6x6 projection + softmax (warp-uniform Ws loads;
    // Ws is 73KB total, L2/L1 hot).
    const float* W = Ws + (size_t)s * (LL * LL);
    float logit[LL];
#pragma unroll
    for (int m = 0; m < LL; m++) logit[m] = 0.0f;
#pragma unroll
    for (int l = 0; l < LL; l++) {
        const float sl = p[l];
#pragma unroll
        for (int m = 0; m < LL; m++) {
            logit[m] = fmaf(sl, __ldg(W + l * LL + m), logit[m]);
        }
    }

    float mx = logit[0];
#pragma unroll
    for (int m = 1; m < LL; m++) mx = fmaxf(mx, logit[m]);
    float a[LL];
    float den = 0.0f;
#pragma unroll
    for (int m = 0; m < LL; m++) {
        a[m] = __expf(logit[m] - mx);
        den += a[m];
    }
    const float inv = __frcp_rn(den);
#pragma unroll
    for (int m = 0; m < LL; m++) a[m] *= inv;

    // Weighted combine over layers, 4 coalesced streaming stores.
#pragma unroll
    for (int c = 0; c < CHNK; c++) {
        float4 o;
        o.x = o.y = o.z = o.w = 0.0f;
#pragma unroll
        for (int j = 0; j < LL; j++) {
            o.x = fmaf(a[j], v[j][c].x, o.x);
            o.y = fmaf(a[j], v[j][c].y, o.y);
            o.z = fmaf(a[j], v[j][c].z, o.z);
            o.w = fmaf(a[j], v[j][c].w, o.w);
        }
        __stcs(reinterpret_cast<float4*>(out + base + c * 128), o);
    }
}

extern "C" void kernel_launch(void* const* d_in, const int* in_sizes, int n_in,
                              void* d_out, int out_size)
{
    const float* x0 = (const float*)d_in[0];
    const float* x1 = (const float*)d_in[1];
    const float* x2 = (const float*)d_in[2];
    const float* x3 = (const float*)d_in[3];
    const float* x4 = (const float*)d_in[4];
    const float* x5 = (const float*)d_in[5];
    const float* Ws = (const float*)d_in[6];
    float* out = (float*)d_out;

    const int rows = in_sizes[0] / DD;          // B*S = 32768
    dense_att_kernel<<<rows / (NTHR / 32), NTHR>>>(x0, x1, x2, x3, x4, x5, Ws, out);
}

// round 9
// speedup vs baseline: 1.0918x; 1.0060x over previous
#include <cuda_runtime.h>

// DenselyCnnAttLayer, CTA == warp == row (finest scheduling granularity).
// out[b,s,d] = sum_l softmax_m( sum_l' s[b,s,l'] * Ws[s,l',m] )[l] * x_l[b,s,d]
// where s[b,s,l] = sum_d x_l[b,s,d].  B=64, S=512, L=6, D=512, fp32.
//
// Traffic is minimal: 6 reads + 1 write = ~470MB; champion (R3/R8) runs at
// 6.73TB/s (85% of spec), ncu 66.3us. R9 tests the last untried knob:
// CTA granularity. With 4-warp CTAs, all 4 warps retire together -- an
// early-finishing warp's resources are held hostage by its slowest sibling.
// With warp==CTA (block=32, grid=32768), resources free per-row and the HW
// scheduler back-fills immediately (up to 32 CTA slots/SM vs 16 warps).
// Per-row work identical to R8: 24 front-batched streaming LDG.128,
// shuffle-tree reduction, redundant per-lane 6x6 softmax, 4 STG.128.

#define DD    512
#define LL    6
#define CHNK  4            // float4 chunks per lane per layer (512/32/4)
#define NTHR  32           // ONE warp per CTA

__global__ __launch_bounds__(NTHR)
void dense_att_kernel(const float* __restrict__ x0,
                      const float* __restrict__ x1,
                      const float* __restrict__ x2,
                      const float* __restrict__ x3,
                      const float* __restrict__ x4,
                      const float* __restrict__ x5,
                      const float* __restrict__ Ws,   // [S, L, L]
                      float* __restrict__ out)        // [B, S, D]
{
    const int lane = threadIdx.x;
    const int row  = blockIdx.x;             // b*S + s
    const int s    = row & 511;              // S = 512

    // lane handles float4s at d = c*128 + lane*4, c = 0..3 (coalesced)
    const size_t base = (size_t)row * DD + (size_t)lane * 4;

    const float* xs[LL] = {x0, x1, x2, x3, x4, x5};

    // 24 front-batched streaming LDG.128 (each element touched exactly once).
    float4 v[LL][CHNK];
#pragma unroll
    for (int j = 0; j < LL; j++) {
#pragma unroll
        for (int c = 0; c < CHNK; c++) {
            v[j][c] = __ldcs(reinterpret_cast<const float4*>(xs[j] + base + c * 128));
        }
    }

    float p[LL];
#pragma unroll
    for (int j = 0; j < LL; j++) {
        float a0 = (v[j][0].x + v[j][0].y) + (v[j][0].z + v[j][0].w);
        float a1 = (v[j][1].x + v[j][1].y) + (v[j][1].z + v[j][1].w);
        float a2 = (v[j][2].x + v[j][2].y) + (v[j][2].z + v[j][2].w);
        float a3 = (v[j][3].x + v[j][3].y) + (v[j][3].z + v[j][3].w);
        p[j] = (a0 + a1) + (a2 + a3);
    }

    // Warp butterfly: all lanes end with the full per-layer sums.
    // (redux.sync.add is integer-only on sm_103 — shuffle tree required.)
#pragma unroll
    for (int off = 16; off > 0; off >>= 1) {
#pragma unroll
        for (int j = 0; j < LL; j++) {
            p[j] += __shfl_xor_sync(0xffffffffu, p[j], off);
        }
    }

    // Redundant per-lane 6x6 projection + softmax (warp-uniform Ws loads;
    // Ws is 73KB total, L2/L1 hot).
    const float* W = Ws + (size_t)s * (LL * LL);
    float logit[LL];
#pragma unroll
    for (int m = 0; m < LL; m++) logit[m] = 0.0f;
#pragma unroll
    for (int l = 0; l < LL; l++) {
        const float sl = p[l];
#pragma unroll
        for (int m = 0; m < LL; m++) {
            logit[m] = fmaf(sl, __ldg(W + l * LL + m), logit[m]);
        }
    }

    float mx = logit[0];
#pragma unroll
    for (int m = 1; m < LL; m++) mx = fmaxf(mx, logit[m]);
    float a[LL];
    float den = 0.0f;
#pragma unroll
    for (int m = 0; m < LL; m++) {
        a[m] = __expf(logit[m] - mx);
        den += a[m];
    }
    const float inv = __frcp_rn(den);
#pragma unroll
    for (int m = 0; m < LL; m++) a[m] *= inv;

    // Weighted combine over layers, 4 coalesced streaming stores.
#pragma unroll
    for (int c = 0; c < CHNK; c++) {
        float4 o;
        o.x = o.y = o.z = o.w = 0.0f;
#pragma unroll
        for (int j = 0; j < LL; j++) {
            o.x = fmaf(a[j], v[j][c].x, o.x);
            o.y = fmaf(a[j], v[j][c].y, o.y);
            o.z = fmaf(a[j], v[j][c].z, o.z);
            o.w = fmaf(a[j], v[j][c].w, o.w);
        }
        __stcs(reinterpret_cast<float4*>(out + base + c * 128), o);
    }
}

extern "C" void kernel_launch(void* const* d_in, const int* in_sizes, int n_in,
                              void* d_out, int out_size)
{
    const float* x0 = (const float*)d_in[0];
    const float* x1 = (const float*)d_in[1];
    const float* x2 = (const float*)d_in[2];
    const float* x3 = (const float*)d_in[3];
    const float* x4 = (const float*)d_in[4];
    const float* x5 = (const float*)d_in[5];
    const float* Ws = (const float*)d_in[6];
    float* out = (float*)d_out;

    const int rows = in_sizes[0] / DD;          // B*S = 32768
    dense_att_kernel<<<rows, NTHR>>>(x0, x1, x2, x3, x4, x5, Ws, out);
}